// round 3
// baseline (speedup 1.0000x reference)
#include <cuda_runtime.h>

// ---------------------------------------------------------------------------
// SSRupsampling: x[4,2048,48,48] ->
//   1x1(w_channel) -> 1x1(w_w) -> pixelshuffle-H -> (3x3 conv+ReLU)x2 on 3-col
//   chunks -> 1x1(w_H) -> pixelshuffle-W -> (3x3 conv+ReLU)x2 on 3-row chunks
// Output [4,512,96,96] fp32.
// All fp32 FFMA this round (accuracy-safe baseline).
// ---------------------------------------------------------------------------

// Scratch buffers (static device globals: allocation-free).
__device__ float g_y1[4 * 512 * 2304];        // after w_channel   (18.9 MB)
__device__ float g_y2[4 * 1024 * 2304];       // after w_w         (37.7 MB)
__device__ float g_xp[4 * 512 * 96 * 48];     // after H-shuffle   (37.7 MB)
__device__ float g_t1[4 * 512 * 96 * 48];     // convLR pass 1
__device__ float g_t2[4 * 512 * 96 * 48];     // convLR pass 2
__device__ float g_y3[4 * 1024 * 96 * 48];    // after w_H         (75.5 MB)
__device__ float g_xh[4 * 512 * 96 * 96];     // after W-shuffle   (75.5 MB)
__device__ float g_t3[4 * 512 * 96 * 96];     // convDU pass 1

// ---------------------------------------------------------------------------
// Batched GEMM: C[z] = A @ B[z].  A: [M,K] row-major (shared across batch),
// B[z]: [K,N] row-major, C[z]: [M,N] row-major.
// Tile 128x128, BK=8, 256 threads, 8x8 per-thread register tile.
// Requires M%128==0, N%128==0, K%8==0 (true for all three call sites).
// ---------------------------------------------------------------------------
__global__ __launch_bounds__(256)
void gemm128(const float* __restrict__ A, const float* __restrict__ B,
             float* __restrict__ C, int M, int N, int K,
             long strideB, long strideC) {
    __shared__ float sA[8][128];   // sA[k][m]
    __shared__ float sB[8][128];   // sB[k][n]

    const int tid = threadIdx.x;
    const int n0 = blockIdx.x * 128;
    const int m0 = blockIdx.y * 128;
    const float* Bb = B + (long)blockIdx.z * strideB;
    float* Cb = C + (long)blockIdx.z * strideC;

    const int tx = tid & 15;          // 16 n-groups of 8
    const int ty = tid >> 4;          // 16 m-groups of 8

    // A loader: row = tid/2 (0..127), kvec = (tid&1)*4
    const int arow = tid >> 1;
    const int akv  = (tid & 1) * 4;
    // B loader: krow = tid/32 (0..7), nvec = (tid&31)*4
    const int brow = tid >> 5;
    const int bnv  = (tid & 31) * 4;

    float acc[8][8];
    #pragma unroll
    for (int i = 0; i < 8; i++)
        #pragma unroll
        for (int j = 0; j < 8; j++) acc[i][j] = 0.f;

    for (int k0 = 0; k0 < K; k0 += 8) {
        float4 av = *(const float4*)&A[(long)(m0 + arow) * K + k0 + akv];
        sA[akv + 0][arow] = av.x;
        sA[akv + 1][arow] = av.y;
        sA[akv + 2][arow] = av.z;
        sA[akv + 3][arow] = av.w;
        *(float4*)&sB[brow][bnv] =
            *(const float4*)&Bb[(long)(k0 + brow) * N + n0 + bnv];
        __syncthreads();

        #pragma unroll
        for (int kk = 0; kk < 8; kk++) {
            float a[8], b[8];
            *(float4*)&a[0] = *(const float4*)&sA[kk][ty * 8];
            *(float4*)&a[4] = *(const float4*)&sA[kk][ty * 8 + 4];
            *(float4*)&b[0] = *(const float4*)&sB[kk][tx * 8];
            *(float4*)&b[4] = *(const float4*)&sB[kk][tx * 8 + 4];
            #pragma unroll
            for (int i = 0; i < 8; i++)
                #pragma unroll
                for (int j = 0; j < 8; j++)
                    acc[i][j] += a[i] * b[j];
        }
        __syncthreads();
    }

    #pragma unroll
    for (int i = 0; i < 8; i++) {
        float* crow = &Cb[(long)(m0 + ty * 8 + i) * N + n0 + tx * 8];
        *(float4*)&crow[0] = make_float4(acc[i][0], acc[i][1], acc[i][2], acc[i][3]);
        *(float4*)&crow[4] = make_float4(acc[i][4], acc[i][5], acc[i][6], acc[i][7]);
    }
}

// ---------------------------------------------------------------------------
// Pixel shuffles (cheap permutes).
// ---------------------------------------------------------------------------
__global__ void shuffleH_kernel(const float* __restrict__ src,
                                float* __restrict__ dst, int total) {
    int i = blockIdx.x * blockDim.x + threadIdx.x;
    if (i >= total) return;
    int w  = i % 48;
    int h2 = (i / 48) % 96;
    int c  = (i / (48 * 96)) % 512;
    int n  = i / (48 * 96 * 512);
    // xp[n,c,h2,w] = y2[n, c + 512*(h2&1), h2>>1, w]
    dst[i] = src[(((long)n * 1024 + c + 512 * (h2 & 1)) * 48 + (h2 >> 1)) * 48 + w];
}

__global__ void shuffleW_kernel(const float* __restrict__ src,
                                float* __restrict__ dst, int total) {
    int i = blockIdx.x * blockDim.x + threadIdx.x;
    if (i >= total) return;
    int w2 = i % 96;
    int h  = (i / 96) % 96;
    int c  = (i / (96 * 96)) % 512;
    int n  = i / (96 * 96 * 512);
    // xh[n,c,h,w2] = y3[n, c + 512*(w2&1), h, w2>>1]
    dst[i] = src[(((long)n * 1024 + c + 512 * (w2 & 1)) * 96 + h) * 48 + (w2 >> 1)];
}

// ---------------------------------------------------------------------------
// Generic chunked 3x3 conv + bias + ReLU, implicit GEMM.
// Logical image per (n, chunk): [C=512][L=96][S=3] with zero padding on L and S.
// Element (n, c, l, s) at: n*nStride + c*cStride + l*lStride + (chunk*3+s)*sStride
// Weight tap (dl, ds): w[co*4608 + ci*9 + dl*tapL + ds*tapS]
//   convLR: long=H (kh), short=W (kw) -> tapL=3, tapS=1, sInner=1 (s is stride-1)
//   convDU: long=W (kw), short=H (kh) -> tapL=1, tapS=3, sInner=0 (l is stride-1)
// Block: 64 couts x (32 L-rows x 3 S) = 64x96 outputs, 256 threads,
// each thread: 4 couts x 2 rows x 3 cols = 24 accumulators. BK = 16.
// ---------------------------------------------------------------------------
__global__ __launch_bounds__(256, 2)
void conv3x3_chunk(const float* __restrict__ in, const float* __restrict__ w,
                   const float* __restrict__ bias, float* __restrict__ out,
                   int nChunks, int cStride, int lStride, int sStride,
                   int nStride, int tapL, int tapS, int sInner) {
    // sW[k][tap][co], padded co-stride 65 for conflict-free stores/loads
    __shared__ float sW[16 * 9 * 65];       // 37,440 B
    __shared__ float sI[16 * 34 * 5];       // 10,880 B  (l halo 34, s padded 5)

    const int tid = threadIdx.x;
    const int co0 = blockIdx.x * 64;
    const int l0  = blockIdx.y * 32;
    const int z   = blockIdx.z;
    const int n     = z / nChunks;
    const int chunk = z % nChunks;
    const long base = (long)n * nStride + (long)chunk * 3 * sStride;

    const int tx = tid & 15;         // 16 L-groups of 2 rows
    const int ty = tid >> 4;         // 16 cout-groups of 4
    const int lp = tx * 2;
    const int ty4 = ty * 4;

    float acc[4][2][3];
    #pragma unroll
    for (int m = 0; m < 4; m++)
        #pragma unroll
        for (int li = 0; li < 2; li++)
            #pragma unroll
            for (int s = 0; s < 3; s++) acc[m][li][s] = 0.f;

    for (int ci0 = 0; ci0 < 512; ci0 += 16) {
        // ---- load weights: 16 ci x 9 taps x 64 co = 9216 values ----
        #pragma unroll
        for (int it = 0; it < 36; it++) {
            int i = tid + it * 256;
            int co  = i / 144;
            int rem = i % 144;          // rem = k*9 + t (consecutive per thread)
            int k = rem / 9;
            int t = rem % 9;
            int dl = t / 3, ds = t % 3;
            sW[rem * 65 + co] =
                w[(long)(co0 + co) * 4608 + (ci0 + k) * 9 + dl * tapL + ds * tapS];
        }
        // ---- load input tile: 16 ci x 34 l x 5 s (zero halo) = 2720 ----
        #pragma unroll
        for (int it = 0; it < 11; it++) {
            int j = tid + it * 256;
            if (j < 2720) {
                int k = j / 170;
                int r = j % 170;
                int l, s;
                if (sInner) { l = r / 5; s = r % 5; }      // LR: s is gmem-contig
                else        { s = r / 34; l = r % 34; }    // DU: l is gmem-contig
                int lr = l0 - 1 + l;
                int sr = s - 1;
                float v = 0.f;
                if (lr >= 0 && lr < 96 && sr >= 0 && sr < 3)
                    v = in[base + (long)(ci0 + k) * cStride + lr * lStride + sr * sStride];
                sI[(k * 34 + l) * 5 + s] = v;
            }
        }
        __syncthreads();

        // ---- compute ----
        #pragma unroll 2
        for (int kk = 0; kk < 16; kk++) {
            float rin[4][5];
            #pragma unroll
            for (int li = 0; li < 4; li++)
                #pragma unroll
                for (int s = 0; s < 5; s++)
                    rin[li][s] = sI[(kk * 34 + lp + li) * 5 + s];
            #pragma unroll
            for (int t = 0; t < 9; t++) {
                const int dl = t / 3, ds = t % 3;
                const float a0 = sW[(kk * 9 + t) * 65 + ty4 + 0];
                const float a1 = sW[(kk * 9 + t) * 65 + ty4 + 1];
                const float a2 = sW[(kk * 9 + t) * 65 + ty4 + 2];
                const float a3 = sW[(kk * 9 + t) * 65 + ty4 + 3];
                #pragma unroll
                for (int li = 0; li < 2; li++)
                    #pragma unroll
                    for (int s = 0; s < 3; s++) {
                        const float iv = rin[li + dl][s + ds];
                        acc[0][li][s] += a0 * iv;
                        acc[1][li][s] += a1 * iv;
                        acc[2][li][s] += a2 * iv;
                        acc[3][li][s] += a3 * iv;
                    }
            }
        }
        __syncthreads();
    }

    // ---- bias + ReLU + store ----
    #pragma unroll
    for (int m = 0; m < 4; m++) {
        const int co = co0 + ty4 + m;
        const float bv = bias[co];
        #pragma unroll
        for (int li = 0; li < 2; li++) {
            const int l = l0 + lp + li;
            #pragma unroll
            for (int s = 0; s < 3; s++) {
                float v = acc[m][li][s] + bv;
                out[base + (long)co * cStride + l * lStride + s * sStride] =
                    fmaxf(v, 0.f);
            }
        }
    }
}

// ---------------------------------------------------------------------------
// kernel_launch
// Inputs (metadata order): x, w_channel, w_w, w_H, w_lr, b_lr, w_du, b_du
// ---------------------------------------------------------------------------
extern "C" void kernel_launch(void* const* d_in, const int* in_sizes, int n_in,
                              void* d_out, int out_size) {
    const float* x         = (const float*)d_in[0];
    const float* w_channel = (const float*)d_in[1];
    const float* w_w       = (const float*)d_in[2];
    const float* w_H       = (const float*)d_in[3];
    const float* w_lr      = (const float*)d_in[4];
    const float* b_lr      = (const float*)d_in[5];
    const float* w_du      = (const float*)d_in[6];
    const float* b_du      = (const float*)d_in[7];
    float* out = (float*)d_out;

    float *y1, *y2, *xp, *t1, *t2, *y3, *xh, *t3;
    cudaGetSymbolAddress((void**)&y1, g_y1);
    cudaGetSymbolAddress((void**)&y2, g_y2);
    cudaGetSymbolAddress((void**)&xp, g_xp);
    cudaGetSymbolAddress((void**)&t1, g_t1);
    cudaGetSymbolAddress((void**)&t2, g_t2);
    cudaGetSymbolAddress((void**)&y3, g_y3);
    cudaGetSymbolAddress((void**)&xh, g_xh);
    cudaGetSymbolAddress((void**)&t3, g_t3);

    const dim3 blk(256);

    // Stage 1: y1 = w_channel @ x    [512,2048]@[2048,2304] per batch
    gemm128<<<dim3(18, 4, 4), blk>>>(w_channel, x, y1, 512, 2304, 2048,
                                     2048L * 2304, 512L * 2304);
    // Stage 2: y2 = w_w @ y1         [1024,512]@[512,2304]
    gemm128<<<dim3(18, 8, 4), blk>>>(w_w, y1, y2, 1024, 2304, 512,
                                     512L * 2304, 1024L * 2304);
    // Stage 3: pixel-shuffle along H: [4,1024,48,48] -> [4,512,96,48]
    shuffleH_kernel<<<(4 * 512 * 96 * 48 + 255) / 256, blk>>>(y2, xp,
                                                              4 * 512 * 96 * 48);
    // Stage 4: convLR x2 (3-col chunks, 16 chunks of width 3)
    conv3x3_chunk<<<dim3(8, 3, 4 * 16), blk>>>(xp, w_lr, b_lr, t1,
        16, 96 * 48, 48, 1, 512 * 96 * 48, 3, 1, 1);
    conv3x3_chunk<<<dim3(8, 3, 4 * 16), blk>>>(t1, w_lr, b_lr, t2,
        16, 96 * 48, 48, 1, 512 * 96 * 48, 3, 1, 1);
    // Stage 5: y3 = w_H @ t2         [1024,512]@[512,4608]
    gemm128<<<dim3(36, 8, 4), blk>>>(w_H, t2, y3, 1024, 4608, 512,
                                     512L * 4608, 1024L * 4608);
    // Stage 6: pixel-shuffle along W: [4,1024,96,48] -> [4,512,96,96]
    shuffleW_kernel<<<(4 * 512 * 96 * 96 + 255) / 256, blk>>>(y3, xh,
                                                              4 * 512 * 96 * 96);
    // Stage 7: convDU x2 (3-row chunks, 32 chunks of height 3)
    conv3x3_chunk<<<dim3(8, 3, 4 * 32), blk>>>(xh, w_du, b_du, t3,
        32, 96 * 96, 1, 96, 512 * 96 * 96, 1, 3, 0);
    conv3x3_chunk<<<dim3(8, 3, 4 * 32), blk>>>(t3, w_du, b_du, out,
        32, 96 * 96, 1, 96, 512 * 96 * 96, 1, 3, 0);
}

// round 5
// speedup vs baseline: 2.7238x; 2.7238x over previous
#include <cuda_runtime.h>
#include <cuda_fp16.h>
#include <cstdint>

// ===========================================================================
// SSRupsampling via classic HMMA (mma.sync m16n8k16 fp16, fp32 accum),
// fp16 3-product split (hi*hi + hi*lo + lo*hi) for fp32-grade accuracy.
// Same stage decomposition as R3: all 7 heavy stages are GEMMs, pixel
// shuffles folded into im2col gathers.
// ===========================================================================

// ------------------------------ scratch -----------------------------------
__device__ __half g_Bhi[36864L * 4608];
__device__ __half g_Blo[36864L * 4608];
__device__ __half g_B2hi[9216 * 512];
__device__ __half g_B2lo[9216 * 512];
__device__ __half g_sBhi[18432 * 512];
__device__ __half g_sBlo[18432 * 512];
__device__ float g_y2[9216 * 1024];
__device__ float g_y3[18432 * 1024];
__device__ float g_c1[18432 * 512];
__device__ float g_c3[36864L * 512];
__device__ __half g_wch_hi[512 * 2048], g_wch_lo[512 * 2048];
__device__ __half g_ww_hi[1024 * 512],  g_ww_lo[1024 * 512];
__device__ __half g_wH_hi[1024 * 512],  g_wH_lo[1024 * 512];
__device__ __half g_wlr_hi[512 * 4608], g_wlr_lo[512 * 4608];
__device__ __half g_wdu_hi[512 * 4608], g_wdu_lo[512 * 4608];

// ------------------------------ helpers -----------------------------------
__device__ __forceinline__ uint32_t smem_u32(const void* p) {
    uint32_t a;
    asm("{ .reg .u64 t; cvta.to.shared.u64 t, %1; cvt.u32.u64 %0, t; }"
        : "=r"(a) : "l"(p));
    return a;
}
__device__ __forceinline__ void ldsm_x4(uint32_t* r, uint32_t addr) {
    asm volatile("ldmatrix.sync.aligned.m8n8.x4.shared.b16 {%0,%1,%2,%3}, [%4];"
                 : "=r"(r[0]), "=r"(r[1]), "=r"(r[2]), "=r"(r[3]) : "r"(addr));
}
__device__ __forceinline__ void mma16816(float* c, const uint32_t* a,
                                         const uint32_t* b) {
    asm volatile(
        "mma.sync.aligned.m16n8k16.row.col.f32.f16.f16.f32 "
        "{%0,%1,%2,%3}, {%4,%5,%6,%7}, {%8,%9}, {%0,%1,%2,%3};"
        : "+f"(c[0]), "+f"(c[1]), "+f"(c[2]), "+f"(c[3])
        : "r"(a[0]), "r"(a[1]), "r"(a[2]), "r"(a[3]), "r"(b[0]), "r"(b[1]));
}
__device__ __forceinline__ void cp16(uint32_t sa, const void* ga) {
    asm volatile("cp.async.cg.shared.global [%0], [%1], 16;"
                 :: "r"(sa), "l"(ga));
}

#define BK 32
#define PITCH 80                      // bytes per smem row: 32 halves + 16B pad
#define TILE_BYTES (128 * PITCH)      // 10240
#define STAGE_BYTES (4 * TILE_BYTES)  // Ahi, Alo, Bhi, Blo
#define SMEM_TOTAL (2 * STAGE_BYTES)  // 81920, double buffered

// ---------------------------------------------------------------------------
// GEMM: D[m, n] = sum_k A[m,k]*B[n,k], fp16 3-product split, fp32 accumulate.
// Block tile 128x128, BK=32, 256 threads (8 warps, 4M x 2N), warp tile 32x64.
// Epilogue modes: 0 fp32 [pix,ld]; 1 fp16-split [pix,ld]; 2 bias+relu fp32;
//                 3 bias+relu fp16-split; 4 bias+relu NCHW scatter (final).
// ---------------------------------------------------------------------------
__global__ __launch_bounds__(256, 2)
void gemm_hmma(const __half* __restrict__ Ahi, const __half* __restrict__ Alo,
               const __half* __restrict__ Bhi, const __half* __restrict__ Blo,
               int K, int mode, const float* __restrict__ bias,
               float* __restrict__ outF, __half* __restrict__ outHi,
               __half* __restrict__ outLo, int ldOut) {
    extern __shared__ char smem[];
    const uint32_t sb = smem_u32(smem);
    const int tid = threadIdx.x;
    const int lane = tid & 31, wid = tid >> 5;
    const int wm = wid >> 1, wn = wid & 1;
    const int m0 = blockIdx.x * 128;
    const long n0 = (long)blockIdx.y * 128;

    const __half* gA0 = Ahi + (long)m0 * K;
    const __half* gA1 = Alo + (long)m0 * K;
    const __half* gB0 = Bhi + n0 * K;
    const __half* gB1 = Blo + n0 * K;

    // loader: per tile, 512 x 16B; thread handles e = tid, tid+256
    const int lrow0 = tid >> 2, lcol = tid & 3;
    const int lrow1 = (tid + 256) >> 2;

    // ldmatrix per-lane offsets (pitch-80 conflict-free layout)
    const int lg = lane >> 3, lr = lane & 7;
    const uint32_t aoff = (uint32_t)(((lg & 1) * 8 + lr) + wm * 32) * PITCH +
                          (lg >> 1) * 16;
    const uint32_t boff = (uint32_t)(((lg >> 1) * 8 + lr) + wn * 64) * PITCH +
                          (lg & 1) * 16;

    float acc[2][8][4];
    #pragma unroll
    for (int i = 0; i < 2; i++)
        #pragma unroll
        for (int j = 0; j < 8; j++)
            #pragma unroll
            for (int c = 0; c < 4; c++) acc[i][j][c] = 0.f;

    const int nC = K / BK;

    // issue stage kc into buffer kc&1
    auto issue = [&](int kc) {
        const uint32_t so = sb + (kc & 1) * STAGE_BYTES;
        const long kb = (long)kc * BK;
        const uint32_t s0 = so + lrow0 * PITCH + lcol * 16;
        const uint32_t s1 = so + lrow1 * PITCH + lcol * 16;
        const long g0 = (long)lrow0 * K + kb + lcol * 8;
        const long g1 = (long)lrow1 * K + kb + lcol * 8;
        cp16(s0 + 0 * TILE_BYTES, gA0 + g0);
        cp16(s1 + 0 * TILE_BYTES, gA0 + g1);
        cp16(s0 + 1 * TILE_BYTES, gA1 + g0);
        cp16(s1 + 1 * TILE_BYTES, gA1 + g1);
        cp16(s0 + 2 * TILE_BYTES, gB0 + g0);
        cp16(s1 + 2 * TILE_BYTES, gB0 + g1);
        cp16(s0 + 3 * TILE_BYTES, gB1 + g0);
        cp16(s1 + 3 * TILE_BYTES, gB1 + g1);
        asm volatile("cp.async.commit_group;" ::: "memory");
    };

    issue(0);
    for (int kc = 0; kc < nC; kc++) {
        if (kc + 1 < nC) {
            issue(kc + 1);
            asm volatile("cp.async.wait_group 1;" ::: "memory");
        } else {
            asm volatile("cp.async.wait_group 0;" ::: "memory");
        }
        __syncthreads();

        const uint32_t so = sb + (kc & 1) * STAGE_BYTES;
        #pragma unroll
        for (int ks = 0; ks < 2; ks++) {
            uint32_t ah[2][4], al[2][4];
            const uint32_t ab = so + aoff + ks * 32;
            ldsm_x4(ah[0], ab);
            ldsm_x4(ah[1], ab + 16 * PITCH);
            ldsm_x4(al[0], ab + TILE_BYTES);
            ldsm_x4(al[1], ab + TILE_BYTES + 16 * PITCH);
            const uint32_t bb = so + 2 * TILE_BYTES + boff + ks * 32;
            #pragma unroll
            for (int p = 0; p < 4; p++) {
                uint32_t bh[4], bl[4];
                ldsm_x4(bh, bb + p * 16 * PITCH);
                ldsm_x4(bl, bb + p * 16 * PITCH + TILE_BYTES);
                #pragma unroll
                for (int mi = 0; mi < 2; mi++) {
                    mma16816(acc[mi][2 * p],     ah[mi], bh);
                    mma16816(acc[mi][2 * p],     ah[mi], bl);
                    mma16816(acc[mi][2 * p],     al[mi], bh);
                    mma16816(acc[mi][2 * p + 1], ah[mi], bh + 2);
                    mma16816(acc[mi][2 * p + 1], ah[mi], bl + 2);
                    mma16816(acc[mi][2 * p + 1], al[mi], bh + 2);
                }
            }
        }
        __syncthreads();
    }

    // ---------------- epilogue -------------------------------------------
    const int mrow = m0 + wm * 32 + (lane >> 2);
    const int nrow = wn * 64 + 2 * (lane & 3);
    #pragma unroll
    for (int mi = 0; mi < 2; mi++) {
        #pragma unroll
        for (int nj = 0; nj < 8; nj++) {
            #pragma unroll
            for (int ci = 0; ci < 4; ci++) {
                const int m = mrow + mi * 16 + (ci >> 1) * 8;
                const long pix = n0 + nrow + nj * 8 + (ci & 1);
                float v = acc[mi][nj][ci];
                if (mode >= 2) v = fmaxf(v + bias[m], 0.f);
                if (mode == 0 || mode == 2) {
                    outF[pix * ldOut + m] = v;
                } else if (mode == 1 || mode == 3) {
                    __half h = __float2half_rn(v);
                    outHi[pix * ldOut + m] = h;
                    outLo[pix * ldOut + m] = __float2half_rn(v - __half2float(h));
                } else {  // mode 4: NCHW scatter (convDU geometry)
                    int img = (int)(pix / 288);
                    int rem = (int)(pix - (long)img * 288);
                    int l = rem / 3, s = rem - l * 3;
                    int nb = img >> 5, ck = img & 31;
                    int h = ck * 3 + s;
                    outF[(((long)nb * 512 + m) * 96 + h) * 96 + l] = v;
                }
            }
        }
    }
}

// ------------------------- split helpers & prep kernels --------------------
__device__ __forceinline__ void split_store(float v, __half* hi, __half* lo,
                                            long idx) {
    __half h = __float2half_rn(v);
    hi[idx] = h;
    lo[idx] = __float2half_rn(v - __half2float(h));
}

__global__ void splitW(const float* __restrict__ src, __half* __restrict__ hi,
                       __half* __restrict__ lo, int count) {
    int i = blockIdx.x * 256 + threadIdx.x;
    if (i < count) split_store(src[i], hi, lo, i);
}

// conv weight reorder + split: dst[co*4608 + t*512 + ci]
__global__ void splitWConv(const float* __restrict__ w, __half* __restrict__ hi,
                           __half* __restrict__ lo, int mulL, int mulS) {
    int i = blockIdx.x * 256 + threadIdx.x;
    int ci = i & 511;
    int t = (i >> 9) % 9;
    int co = i / 4608;
    int dl = t / 3, ds = t % 3;
    float v = w[(long)co * 4608 + ci * 9 + dl * mulL + ds * mulS];
    split_store(v, hi, lo, (long)co * 4608 + t * 512 + ci);
}

// x[n,c,h,w] -> B[pix(n,h,w), c] split
__global__ void gatherX(const float* __restrict__ x, __half* __restrict__ bhi,
                        __half* __restrict__ blo) {
    int i = blockIdx.x * 256 + threadIdx.x;
    int c4 = i & 511;
    int pix = i >> 9;
    int n = pix / 2304;
    int p = pix - n * 2304;
    const float* xs = x + ((long)n * 2048 + c4 * 4) * 2304 + p;
    long o = (long)pix * 2048 + c4 * 4;
    split_store(xs[0],    bhi, blo, o + 0);
    split_store(xs[2304], bhi, blo, o + 1);
    split_store(xs[4608], bhi, blo, o + 2);
    split_store(xs[6912], bhi, blo, o + 3);
}

// im2col gather (no shuffle): src [Npix, 512], pix = img*288 + l*3 + s
__global__ void gatherConv(const float* __restrict__ src,
                           __half* __restrict__ bhi,
                           __half* __restrict__ blo, int total) {
    int i = blockIdx.x * 256 + threadIdx.x;
    if (i >= total) return;
    int ci4 = i & 127;
    int t = (i >> 7) % 9;
    int pix = i / 1152;
    int s = pix % 3, l = (pix / 3) % 96, img = pix / 288;
    int ll = l + t / 3 - 1, ss = s + t % 3 - 1;
    float4 v = make_float4(0.f, 0.f, 0.f, 0.f);
    if (ll >= 0 && ll < 96 && ss >= 0 && ss < 3)
        v = *(const float4*)(src + ((long)(img * 288 + ll * 3 + ss) * 512 + ci4 * 4));
    long o = (long)pix * 4608 + t * 512 + ci4 * 4;
    split_store(v.x, bhi, blo, o + 0);
    split_store(v.y, bhi, blo, o + 1);
    split_store(v.z, bhi, blo, o + 2);
    split_store(v.w, bhi, blo, o + 3);
}

// convLR im2col fused with H-pixel-shuffle. src = y2 [pix2(n,h,w), 1024].
__global__ void gatherShufLR(const float* __restrict__ y2,
                             __half* __restrict__ bhi,
                             __half* __restrict__ blo, int total) {
    int i = blockIdx.x * 256 + threadIdx.x;
    if (i >= total) return;
    int ci4 = i & 127;
    int t = (i >> 7) % 9;
    int pix = i / 1152;
    int s = pix % 3, l = (pix / 3) % 96, img = pix / 288;
    int ll = l + t / 3 - 1, ss = s + t % 3 - 1;   // ll = h2, ss = w-in-chunk
    float4 v = make_float4(0.f, 0.f, 0.f, 0.f);
    if (ll >= 0 && ll < 96 && ss >= 0 && ss < 3) {
        int n = img >> 4, ckW = img & 15;
        int w = ckW * 3 + ss;
        int ch = ci4 * 4 + ((ll & 1) << 9);
        v = *(const float4*)(y2 + ((long)(n * 2304 + (ll >> 1) * 48 + w) * 1024 + ch));
    }
    long o = (long)pix * 4608 + t * 512 + ci4 * 4;
    split_store(v.x, bhi, blo, o + 0);
    split_store(v.y, bhi, blo, o + 1);
    split_store(v.z, bhi, blo, o + 2);
    split_store(v.w, bhi, blo, o + 3);
}

// convDU im2col fused with W-pixel-shuffle. src = y3 [pixLR, 1024].
__global__ void gatherShufDU(const float* __restrict__ y3,
                             __half* __restrict__ bhi,
                             __half* __restrict__ blo, int total) {
    int i = blockIdx.x * 256 + threadIdx.x;
    if (i >= total) return;
    int ci4 = i & 127;
    int t = (i >> 7) % 9;
    int pix = i / 1152;
    int s = pix % 3, l = (pix / 3) % 96, img = pix / 288;
    int ll = l + t / 3 - 1, ss = s + t % 3 - 1;   // ll = w2, ss = h-in-chunk
    float4 v = make_float4(0.f, 0.f, 0.f, 0.f);
    if (ll >= 0 && ll < 96 && ss >= 0 && ss < 3) {
        int n = img >> 5, ckH = img & 31;
        int h = ckH * 3 + ss;
        int ch = ci4 * 4 + ((ll & 1) << 9);
        int w = ll >> 1;
        int pixLR = (n * 16 + w / 3) * 288 + h * 3 + (w % 3);
        v = *(const float4*)(y3 + ((long)pixLR * 1024 + ch));
    }
    long o = (long)pix * 4608 + t * 512 + ci4 * 4;
    split_store(v.x, bhi, blo, o + 0);
    split_store(v.y, bhi, blo, o + 1);
    split_store(v.z, bhi, blo, o + 2);
    split_store(v.w, bhi, blo, o + 3);
}

// ---------------------------------------------------------------------------
// kernel_launch.  Inputs: x, w_channel, w_w, w_H, w_lr, b_lr, w_du, b_du
// ---------------------------------------------------------------------------
extern "C" void kernel_launch(void* const* d_in, const int* in_sizes, int n_in,
                              void* d_out, int out_size) {
    const float* x         = (const float*)d_in[0];
    const float* w_channel = (const float*)d_in[1];
    const float* w_w       = (const float*)d_in[2];
    const float* w_H       = (const float*)d_in[3];
    const float* w_lr      = (const float*)d_in[4];
    const float* b_lr      = (const float*)d_in[5];
    const float* w_du      = (const float*)d_in[6];
    const float* b_du      = (const float*)d_in[7];
    float* out = (float*)d_out;

    __half *Bhi, *Blo, *B2hi, *B2lo, *sBhi, *sBlo;
    __half *wch_hi, *wch_lo, *ww_hi, *ww_lo, *wH_hi, *wH_lo;
    __half *wlr_hi, *wlr_lo, *wdu_hi, *wdu_lo;
    float *y2, *y3, *c1, *c3;
    cudaGetSymbolAddress((void**)&Bhi, g_Bhi);
    cudaGetSymbolAddress((void**)&Blo, g_Blo);
    cudaGetSymbolAddress((void**)&B2hi, g_B2hi);
    cudaGetSymbolAddress((void**)&B2lo, g_B2lo);
    cudaGetSymbolAddress((void**)&sBhi, g_sBhi);
    cudaGetSymbolAddress((void**)&sBlo, g_sBlo);
    cudaGetSymbolAddress((void**)&y2, g_y2);
    cudaGetSymbolAddress((void**)&y3, g_y3);
    cudaGetSymbolAddress((void**)&c1, g_c1);
    cudaGetSymbolAddress((void**)&c3, g_c3);
    cudaGetSymbolAddress((void**)&wch_hi, g_wch_hi);
    cudaGetSymbolAddress((void**)&wch_lo, g_wch_lo);
    cudaGetSymbolAddress((void**)&ww_hi, g_ww_hi);
    cudaGetSymbolAddress((void**)&ww_lo, g_ww_lo);
    cudaGetSymbolAddress((void**)&wH_hi, g_wH_hi);
    cudaGetSymbolAddress((void**)&wH_lo, g_wH_lo);
    cudaGetSymbolAddress((void**)&wlr_hi, g_wlr_hi);
    cudaGetSymbolAddress((void**)&wlr_lo, g_wlr_lo);
    cudaGetSymbolAddress((void**)&wdu_hi, g_wdu_hi);
    cudaGetSymbolAddress((void**)&wdu_lo, g_wdu_lo);

    cudaFuncSetAttribute(gemm_hmma, cudaFuncAttributeMaxDynamicSharedMemorySize,
                         SMEM_TOTAL);

    // weight prep
    splitW<<<(512 * 2048) / 256, 256>>>(w_channel, wch_hi, wch_lo, 512 * 2048);
    splitW<<<(1024 * 512) / 256, 256>>>(w_w, ww_hi, ww_lo, 1024 * 512);
    splitW<<<(1024 * 512) / 256, 256>>>(w_H, wH_hi, wH_lo, 1024 * 512);
    splitWConv<<<(512 * 4608) / 256, 256>>>(w_lr, wlr_hi, wlr_lo, 3, 1);
    splitWConv<<<(512 * 4608) / 256, 256>>>(w_du, wdu_hi, wdu_lo, 1, 3);

    // stage 1: y1 = w_channel @ x  (M=512, K=2048, N=9216) -> split B2
    gatherX<<<(9216 * 512) / 256, 256>>>(x, Bhi, Blo);
    gemm_hmma<<<dim3(4, 72), 256, SMEM_TOTAL>>>(
        wch_hi, wch_lo, Bhi, Blo, 2048, 1, nullptr, nullptr, B2hi, B2lo, 512);

    // stage 2: y2 = w_w @ y1  (M=1024, K=512, N=9216) -> fp32
    gemm_hmma<<<dim3(8, 72), 256, SMEM_TOTAL>>>(
        ww_hi, ww_lo, B2hi, B2lo, 512, 0, nullptr, y2, nullptr, nullptr, 1024);

    // convLR pass 1: shuffle-H + im2col, GEMM (M=512, K=4608, N=18432)
    const int totLR = 18432 * 1152;
    gatherShufLR<<<totLR / 256, 256>>>(y2, Bhi, Blo, totLR);
    gemm_hmma<<<dim3(4, 144), 256, SMEM_TOTAL>>>(
        wlr_hi, wlr_lo, Bhi, Blo, 4608, 2, b_lr, c1, nullptr, nullptr, 512);

    // convLR pass 2 -> split into sB (w_H's B)
    gatherConv<<<totLR / 256, 256>>>(c1, Bhi, Blo, totLR);
    gemm_hmma<<<dim3(4, 144), 256, SMEM_TOTAL>>>(
        wlr_hi, wlr_lo, Bhi, Blo, 4608, 3, b_lr, nullptr, sBhi, sBlo, 512);

    // w_H stage: y3 = w_H @ c2  (M=1024, K=512, N=18432) -> fp32
    gemm_hmma<<<dim3(8, 144), 256, SMEM_TOTAL>>>(
        wH_hi, wH_lo, sBhi, sBlo, 512, 0, nullptr, y3, nullptr, nullptr, 1024);

    // convDU pass 1: shuffle-W + im2col, GEMM (M=512, K=4608, N=36864)
    const int totDU = 36864 * 1152;
    gatherShufDU<<<totDU / 256, 256>>>(y3, Bhi, Blo, totDU);
    gemm_hmma<<<dim3(4, 288), 256, SMEM_TOTAL>>>(
        wdu_hi, wdu_lo, Bhi, Blo, 4608, 2, b_du, c3, nullptr, nullptr, 512);

    // convDU pass 2 -> final NCHW output
    gatherConv<<<totDU / 256, 256>>>(c3, Bhi, Blo, totDU);
    gemm_hmma<<<dim3(4, 288), 256, SMEM_TOTAL>>>(
        wdu_hi, wdu_lo, Bhi, Blo, 4608, 4, b_du, out, nullptr, nullptr, 0);
}

// round 6
// speedup vs baseline: 3.5309x; 1.2963x over previous
#include <cuda_runtime.h>
#include <cuda_fp16.h>
#include <cstdint>

// ===========================================================================
// SSRupsampling via HMMA (mma.sync m16n8k16, fp32 accum), fp16 3-product
// split. Conv stages read B as SHIFTED VIEWS of the compact [pix,512]
// activation (tap t = row shift t-4, boundary-masked) -- no im2col expansion.
// ===========================================================================

// ------------------------------ scratch -----------------------------------
__device__ __half g_aHi[36864L * 512], g_aLo[36864L * 512];
__device__ __half g_bHi[36864L * 512], g_bLo[36864L * 512];
__device__ __half g_cHi[18432 * 512],  g_cLo[18432 * 512];
__device__ __half g_B2hi[9216 * 512],  g_B2lo[9216 * 512];
__device__ float g_y2[9216 * 1024];
__device__ float g_y3[18432 * 1024];
__device__ __half g_wch_hi[512 * 2048], g_wch_lo[512 * 2048];
__device__ __half g_ww_hi[1024 * 512],  g_ww_lo[1024 * 512];
__device__ __half g_wH_hi[1024 * 512],  g_wH_lo[1024 * 512];
__device__ __half g_wlr_hi[512 * 4608], g_wlr_lo[512 * 4608];
__device__ __half g_wdu_hi[512 * 4608], g_wdu_lo[512 * 4608];

// ------------------------------ helpers -----------------------------------
__device__ __forceinline__ uint32_t smem_u32(const void* p) {
    uint32_t a;
    asm("{ .reg .u64 t; cvta.to.shared.u64 t, %1; cvt.u32.u64 %0, t; }"
        : "=r"(a) : "l"(p));
    return a;
}
__device__ __forceinline__ void ldsm_x4(uint32_t* r, uint32_t addr) {
    asm volatile("ldmatrix.sync.aligned.m8n8.x4.shared.b16 {%0,%1,%2,%3}, [%4];"
                 : "=r"(r[0]), "=r"(r[1]), "=r"(r[2]), "=r"(r[3]) : "r"(addr));
}
__device__ __forceinline__ void mma16816(float* c, const uint32_t* a,
                                         const uint32_t* b) {
    asm volatile(
        "mma.sync.aligned.m16n8k16.row.col.f32.f16.f16.f32 "
        "{%0,%1,%2,%3}, {%4,%5,%6,%7}, {%8,%9}, {%0,%1,%2,%3};"
        : "+f"(c[0]), "+f"(c[1]), "+f"(c[2]), "+f"(c[3])
        : "r"(a[0]), "r"(a[1]), "r"(a[2]), "r"(a[3]), "r"(b[0]), "r"(b[1]));
}
__device__ __forceinline__ void cp16(uint32_t sa, const void* ga) {
    asm volatile("cp.async.cg.shared.global [%0], [%1], 16;"
                 :: "r"(sa), "l"(ga));
}
__device__ __forceinline__ void cp16p(uint32_t sa, const void* ga, int sz) {
    asm volatile("cp.async.cg.shared.global [%0], [%1], 16, %2;"
                 :: "r"(sa), "l"(ga), "r"(sz));
}

#define BK 32
#define PITCH 80
#define TILE_BYTES (128 * PITCH)
#define STAGE_BYTES (4 * TILE_BYTES)
#define SMEM_TOTAL (2 * STAGE_BYTES)   // 81920

// ---------------------------------------------------------------------------
// GEMM: D[m,n] = sum_k A[m,k]*B[n,k], fp16 x3 split, fp32 accum.
// If conv!=0: K=4608 logical (9 taps x 512), B read from [Npix, 512] with
// row shift (t-4) and boundary mask.  Kb = B row stride in elements.
// Modes: 0 fp32 [pix,ld]; 1 split [pix,ld]; 3 bias+relu split; 4 bias+relu
// NCHW scatter (final convDU output).
// ---------------------------------------------------------------------------
__global__ __launch_bounds__(256, 2)
void gemm_hmma(const __half* __restrict__ Ahi, const __half* __restrict__ Alo,
               const __half* __restrict__ Bhi, const __half* __restrict__ Blo,
               int K, int Kb, int conv, int mode,
               const float* __restrict__ bias, float* __restrict__ outF,
               __half* __restrict__ outHi, __half* __restrict__ outLo,
               int ldOut) {
    extern __shared__ char smem[];
    const uint32_t sb = smem_u32(smem);
    const int tid = threadIdx.x;
    const int lane = tid & 31, wid = tid >> 5;
    const int wm = wid >> 1, wn = wid & 1;
    const int m0 = blockIdx.x * 128;
    const long n0 = (long)blockIdx.y * 128;

    const __half* gA0 = Ahi + (long)m0 * K;
    const __half* gA1 = Alo + (long)m0 * K;
    const __half* gB0 = Bhi + n0 * Kb;
    const __half* gB1 = Blo + n0 * Kb;

    const int lrow0 = tid >> 2, lcol = tid & 3;
    const int lrow1 = lrow0 + 64;

    // conv B-row geometry (pix = img*288 + l*3 + s)
    int l0 = 0, s0 = 0, l1 = 0, s1 = 0;
    if (conv) {
        const int p0 = (int)n0 + lrow0, p1 = (int)n0 + lrow1;
        s0 = p0 % 3; l0 = (p0 / 3) % 96;
        s1 = p1 % 3; l1 = (p1 / 3) % 96;
    }

    const int lg = lane >> 3, lr = lane & 7;
    const uint32_t aoff = (uint32_t)(((lg & 1) * 8 + lr) + wm * 32) * PITCH +
                          (lg >> 1) * 16;
    const uint32_t boff = (uint32_t)(((lg >> 1) * 8 + lr) + wn * 64) * PITCH +
                          (lg & 1) * 16;

    float acc[2][8][4];
    #pragma unroll
    for (int i = 0; i < 2; i++)
        #pragma unroll
        for (int j = 0; j < 8; j++)
            #pragma unroll
            for (int c = 0; c < 4; c++) acc[i][j][c] = 0.f;

    const int nC = K / BK;

    auto issue = [&](int kc) {
        const uint32_t so = sb + (kc & 1) * STAGE_BYTES;
        const uint32_t s0a = so + lrow0 * PITCH + lcol * 16;
        const uint32_t s1a = so + lrow1 * PITCH + lcol * 16;
        // A: always linear in k
        {
            const long kb = (long)kc * BK;
            const long ga0 = (long)lrow0 * K + kb + lcol * 8;
            const long ga1 = (long)lrow1 * K + kb + lcol * 8;
            cp16(s0a + 0 * TILE_BYTES, gA0 + ga0);
            cp16(s1a + 0 * TILE_BYTES, gA0 + ga1);
            cp16(s0a + 1 * TILE_BYTES, gA1 + ga0);
            cp16(s1a + 1 * TILE_BYTES, gA1 + ga1);
        }
        // B: shifted view for conv, linear otherwise
        if (conv) {
            const int t = kc >> 4;                // tap 0..8
            const int dlm = t / 3 - 1, dsm = t % 3 - 1;
            const int koff = (kc & 15) * 32 + lcol * 8;
            const long rs = (long)(t - 4) * Kb;
            const int v0 = ((unsigned)(l0 + dlm) < 96u &&
                            (unsigned)(s0 + dsm) < 3u) ? 16 : 0;
            const int v1 = ((unsigned)(l1 + dlm) < 96u &&
                            (unsigned)(s1 + dsm) < 3u) ? 16 : 0;
            const long gb0 = (long)lrow0 * Kb + rs + koff;
            const long gb1 = (long)lrow1 * Kb + rs + koff;
            cp16p(s0a + 2 * TILE_BYTES, gB0 + gb0, v0);
            cp16p(s1a + 2 * TILE_BYTES, gB0 + gb1, v1);
            cp16p(s0a + 3 * TILE_BYTES, gB1 + gb0, v0);
            cp16p(s1a + 3 * TILE_BYTES, gB1 + gb1, v1);
        } else {
            const long kb = (long)kc * BK;
            const long gb0 = (long)lrow0 * Kb + kb + lcol * 8;
            const long gb1 = (long)lrow1 * Kb + kb + lcol * 8;
            cp16(s0a + 2 * TILE_BYTES, gB0 + gb0);
            cp16(s1a + 2 * TILE_BYTES, gB0 + gb1);
            cp16(s0a + 3 * TILE_BYTES, gB1 + gb0);
            cp16(s1a + 3 * TILE_BYTES, gB1 + gb1);
        }
        asm volatile("cp.async.commit_group;" ::: "memory");
    };

    issue(0);
    for (int kc = 0; kc < nC; kc++) {
        if (kc + 1 < nC) {
            issue(kc + 1);
            asm volatile("cp.async.wait_group 1;" ::: "memory");
        } else {
            asm volatile("cp.async.wait_group 0;" ::: "memory");
        }
        __syncthreads();

        const uint32_t so = sb + (kc & 1) * STAGE_BYTES;
        #pragma unroll
        for (int ks = 0; ks < 2; ks++) {
            uint32_t ah[2][4], al[2][4];
            const uint32_t ab = so + aoff + ks * 32;
            ldsm_x4(ah[0], ab);
            ldsm_x4(ah[1], ab + 16 * PITCH);
            ldsm_x4(al[0], ab + TILE_BYTES);
            ldsm_x4(al[1], ab + TILE_BYTES + 16 * PITCH);
            const uint32_t bb = so + 2 * TILE_BYTES + boff + ks * 32;
            #pragma unroll
            for (int p = 0; p < 4; p++) {
                uint32_t bh[4], bl[4];
                ldsm_x4(bh, bb + p * 16 * PITCH);
                ldsm_x4(bl, bb + p * 16 * PITCH + TILE_BYTES);
                #pragma unroll
                for (int mi = 0; mi < 2; mi++) {
                    mma16816(acc[mi][2 * p],     ah[mi], bh);
                    mma16816(acc[mi][2 * p],     ah[mi], bl);
                    mma16816(acc[mi][2 * p],     al[mi], bh);
                    mma16816(acc[mi][2 * p + 1], ah[mi], bh + 2);
                    mma16816(acc[mi][2 * p + 1], ah[mi], bl + 2);
                    mma16816(acc[mi][2 * p + 1], al[mi], bh + 2);
                }
            }
        }
        __syncthreads();
    }

    // ---------------- epilogue -------------------------------------------
    const int mrow = m0 + wm * 32 + (lane >> 2);
    const int nrow = wn * 64 + 2 * (lane & 3);
    #pragma unroll
    for (int mi = 0; mi < 2; mi++) {
        #pragma unroll
        for (int nj = 0; nj < 8; nj++) {
            #pragma unroll
            for (int ci = 0; ci < 4; ci++) {
                const int m = mrow + mi * 16 + (ci >> 1) * 8;
                const long pix = n0 + nrow + nj * 8 + (ci & 1);
                float v = acc[mi][nj][ci];
                if (mode >= 3) v = fmaxf(v + bias[m], 0.f);
                if (mode == 0) {
                    outF[pix * ldOut + m] = v;
                } else if (mode == 1 || mode == 3) {
                    __half h = __float2half_rn(v);
                    outHi[pix * ldOut + m] = h;
                    outLo[pix * ldOut + m] = __float2half_rn(v - __half2float(h));
                } else {  // mode 4: NCHW scatter (convDU geometry)
                    int img = (int)(pix / 288);
                    int rem = (int)(pix - (long)img * 288);
                    int l = rem / 3, s = rem - l * 3;
                    int nb = img >> 5, ck = img & 31;
                    int h = ck * 3 + s;
                    outF[(((long)nb * 512 + m) * 96 + h) * 96 + l] = v;
                }
            }
        }
    }
}

// ------------------------- split helpers & prep kernels --------------------
__device__ __forceinline__ void split_store(float v, __half* hi, __half* lo,
                                            long idx) {
    __half h = __float2half_rn(v);
    hi[idx] = h;
    lo[idx] = __float2half_rn(v - __half2float(h));
}

__global__ void splitW(const float* __restrict__ src, __half* __restrict__ hi,
                       __half* __restrict__ lo, int count) {
    int i = blockIdx.x * 256 + threadIdx.x;
    if (i < count) split_store(src[i], hi, lo, i);
}

// conv weight reorder + split: dst[co*4608 + t*512 + ci]
__global__ void splitWConv(const float* __restrict__ w, __half* __restrict__ hi,
                           __half* __restrict__ lo, int mulL, int mulS) {
    int i = blockIdx.x * 256 + threadIdx.x;
    int ci = i & 511;
    int t = (i >> 9) % 9;
    int co = i / 4608;
    int dl = t / 3, ds = t % 3;
    float v = w[(long)co * 4608 + ci * 9 + dl * mulL + ds * mulS];
    split_store(v, hi, lo, (long)co * 4608 + t * 512 + ci);
}

// x[n,c,h,w] -> B[pix(n,h,w), c] split
__global__ void gatherX(const float* __restrict__ x, __half* __restrict__ bhi,
                        __half* __restrict__ blo) {
    int i = blockIdx.x * 256 + threadIdx.x;
    int c4 = i & 511;
    int pix = i >> 9;
    int n = pix / 2304;
    int p = pix - n * 2304;
    const float* xs = x + ((long)n * 2048 + c4 * 4) * 2304 + p;
    long o = (long)pix * 2048 + c4 * 4;
    split_store(xs[0],    bhi, blo, o + 0);
    split_store(xs[2304], bhi, blo, o + 1);
    split_store(xs[4608], bhi, blo, o + 2);
    split_store(xs[6912], bhi, blo, o + 3);
}

// y2 [pix2(n,h,w), 1024] -> shuffled-H split act [pixLR, 512]
__global__ void shufSplitLR(const float* __restrict__ y2,
                            __half* __restrict__ bhi,
                            __half* __restrict__ blo) {
    int i = blockIdx.x * 256 + threadIdx.x;   // over 18432*128
    int ci4 = i & 127;
    int pix = i >> 7;
    int s = pix % 3, l = (pix / 3) % 96, img = pix / 288;
    int n = img >> 4, ckW = img & 15;
    int w = ckW * 3 + s;
    int ch = ci4 * 4 + ((l & 1) << 9);
    float4 v = *(const float4*)(y2 + ((long)(n * 2304 + (l >> 1) * 48 + w) * 1024 + ch));
    long o = (long)pix * 512 + ci4 * 4;
    split_store(v.x, bhi, blo, o + 0);
    split_store(v.y, bhi, blo, o + 1);
    split_store(v.z, bhi, blo, o + 2);
    split_store(v.w, bhi, blo, o + 3);
}

// y3 [pixLR, 1024] -> shuffled-W split act [pixDU, 512]
__global__ void shufSplitDU(const float* __restrict__ y3,
                            __half* __restrict__ bhi,
                            __half* __restrict__ blo) {
    int i = blockIdx.x * 256 + threadIdx.x;   // over 36864*128
    int ci4 = i & 127;
    int pix = i >> 7;
    int s = pix % 3, l = (pix / 3) % 96, img = pix / 288;
    int n = img >> 5, ckH = img & 31;
    int h = ckH * 3 + s;
    int ch = ci4 * 4 + ((l & 1) << 9);
    int w = l >> 1;
    int pixLR = (n * 16 + w / 3) * 288 + h * 3 + (w % 3);
    float4 v = *(const float4*)(y3 + ((long)pixLR * 1024 + ch));
    long o = (long)pix * 512 + ci4 * 4;
    split_store(v.x, bhi, blo, o + 0);
    split_store(v.y, bhi, blo, o + 1);
    split_store(v.z, bhi, blo, o + 2);
    split_store(v.w, bhi, blo, o + 3);
}

// ---------------------------------------------------------------------------
// kernel_launch.  Inputs: x, w_channel, w_w, w_H, w_lr, b_lr, w_du, b_du
// ---------------------------------------------------------------------------
extern "C" void kernel_launch(void* const* d_in, const int* in_sizes, int n_in,
                              void* d_out, int out_size) {
    const float* x         = (const float*)d_in[0];
    const float* w_channel = (const float*)d_in[1];
    const float* w_w       = (const float*)d_in[2];
    const float* w_H       = (const float*)d_in[3];
    const float* w_lr      = (const float*)d_in[4];
    const float* b_lr      = (const float*)d_in[5];
    const float* w_du      = (const float*)d_in[6];
    const float* b_du      = (const float*)d_in[7];
    float* out = (float*)d_out;

    __half *aHi, *aLo, *bHi, *bLo, *cHi, *cLo, *B2hi, *B2lo;
    __half *wch_hi, *wch_lo, *ww_hi, *ww_lo, *wH_hi, *wH_lo;
    __half *wlr_hi, *wlr_lo, *wdu_hi, *wdu_lo;
    float *y2, *y3;
    cudaGetSymbolAddress((void**)&aHi, g_aHi);
    cudaGetSymbolAddress((void**)&aLo, g_aLo);
    cudaGetSymbolAddress((void**)&bHi, g_bHi);
    cudaGetSymbolAddress((void**)&bLo, g_bLo);
    cudaGetSymbolAddress((void**)&cHi, g_cHi);
    cudaGetSymbolAddress((void**)&cLo, g_cLo);
    cudaGetSymbolAddress((void**)&B2hi, g_B2hi);
    cudaGetSymbolAddress((void**)&B2lo, g_B2lo);
    cudaGetSymbolAddress((void**)&y2, g_y2);
    cudaGetSymbolAddress((void**)&y3, g_y3);
    cudaGetSymbolAddress((void**)&wch_hi, g_wch_hi);
    cudaGetSymbolAddress((void**)&wch_lo, g_wch_lo);
    cudaGetSymbolAddress((void**)&ww_hi, g_ww_hi);
    cudaGetSymbolAddress((void**)&ww_lo, g_ww_lo);
    cudaGetSymbolAddress((void**)&wH_hi, g_wH_hi);
    cudaGetSymbolAddress((void**)&wH_lo, g_wH_lo);
    cudaGetSymbolAddress((void**)&wlr_hi, g_wlr_hi);
    cudaGetSymbolAddress((void**)&wlr_lo, g_wlr_lo);
    cudaGetSymbolAddress((void**)&wdu_hi, g_wdu_hi);
    cudaGetSymbolAddress((void**)&wdu_lo, g_wdu_lo);

    cudaFuncSetAttribute(gemm_hmma, cudaFuncAttributeMaxDynamicSharedMemorySize,
                         SMEM_TOTAL);

    // weight prep
    splitW<<<(512 * 2048) / 256, 256>>>(w_channel, wch_hi, wch_lo, 512 * 2048);
    splitW<<<(1024 * 512) / 256, 256>>>(w_w, ww_hi, ww_lo, 1024 * 512);
    splitW<<<(1024 * 512) / 256, 256>>>(w_H, wH_hi, wH_lo, 1024 * 512);
    splitWConv<<<(512 * 4608) / 256, 256>>>(w_lr, wlr_hi, wlr_lo, 3, 1);
    splitWConv<<<(512 * 4608) / 256, 256>>>(w_du, wdu_hi, wdu_lo, 1, 3);

    // stage 1: split(x) -> a; y1 = w_channel @ x -> split B2 [9216,512]
    gatherX<<<(9216 * 512) / 256, 256>>>(x, aHi, aLo);
    gemm_hmma<<<dim3(4, 72), 256, SMEM_TOTAL>>>(
        wch_hi, wch_lo, aHi, aLo, 2048, 2048, 0, 1, nullptr,
        nullptr, B2hi, B2lo, 512);

    // stage 2: y2 = w_w @ y1 -> fp32 [9216,1024]
    gemm_hmma<<<dim3(8, 72), 256, SMEM_TOTAL>>>(
        ww_hi, ww_lo, B2hi, B2lo, 512, 512, 0, 0, nullptr,
        y2, nullptr, nullptr, 1024);

    // convLR pass 1: shuffle-H + split -> a; conv GEMM -> split b
    shufSplitLR<<<(18432 * 128) / 256, 256>>>(y2, aHi, aLo);
    gemm_hmma<<<dim3(4, 144), 256, SMEM_TOTAL>>>(
        wlr_hi, wlr_lo, aHi, aLo, 4608, 512, 1, 3, b_lr,
        nullptr, bHi, bLo, 512);

    // convLR pass 2: conv GEMM -> split c (w_H's B)
    gemm_hmma<<<dim3(4, 144), 256, SMEM_TOTAL>>>(
        wlr_hi, wlr_lo, bHi, bLo, 4608, 512, 1, 3, b_lr,
        nullptr, cHi, cLo, 512);

    // w_H stage: y3 = w_H @ c -> fp32 [18432,1024]
    gemm_hmma<<<dim3(8, 144), 256, SMEM_TOTAL>>>(
        wH_hi, wH_lo, cHi, cLo, 512, 512, 0, 0, nullptr,
        y3, nullptr, nullptr, 1024);

    // convDU pass 1: shuffle-W + split -> a; conv GEMM -> split b
    shufSplitDU<<<(36864 * 128) / 256, 256>>>(y3, aHi, aLo);
    gemm_hmma<<<dim3(4, 288), 256, SMEM_TOTAL>>>(
        wdu_hi, wdu_lo, aHi, aLo, 4608, 512, 1, 3, b_du,
        nullptr, bHi, bLo, 512);

    // convDU pass 2: conv GEMM -> final NCHW output
    gemm_hmma<<<dim3(4, 288), 256, SMEM_TOTAL>>>(
        wdu_hi, wdu_lo, bHi, bLo, 4608, 512, 1, 4, b_du,
        out, nullptr, nullptr, 0);
}